// round 1
// baseline (speedup 1.0000x reference)
#include <cuda_runtime.h>
#include <math.h>

#define DIM   1152
#define HEADS 16
#define HD    72
#define HDE   73
#define HID   4608
#define HID2  9216
#define BB    2
#define NN    4096
#define MM    (BB*NN)        // 8192
#define TEMB6 (6*DIM)

// ---------------- scratch (device globals; no allocation) ----------------
__device__ float g_x[MM*DIM];        // modulated input (reused for MLP branch)
__device__ float g_q[MM*DIM];
__device__ float g_k[MM*DIM];
__device__ float g_v[MM*DIM];
__device__ float g_attn[MM*DIM];
__device__ float g_h2[MM*DIM];       // hidden after attention residual
__device__ float g_y[(size_t)MM*HID2];  // inverted conv output (302 MB)
__device__ float g_z[(size_t)MM*HID];   // after dw-conv + GLU
__device__ float g_kvp[8*BB*HEADS*HD*HDE];  // split-K partials
__device__ float g_kv[BB*HEADS*HD*HDE];

// ---------------- adaLN modulation + RMSNorm ----------------
// out = rms(in) * (1 + scale) + shift, scale/shift = sst[idx]+temb slice
__global__ void __launch_bounds__(288) modrms_kernel(
    const float* __restrict__ in, const float* __restrict__ temb,
    const float* __restrict__ sst, float* __restrict__ out, int idx0)
{
    int row = blockIdx.x;                 // 0..8191
    int b   = row >> 12;                  // /4096
    const float* ip = in + (size_t)row*DIM;
    int d = threadIdx.x * 4;
    float4 h = *(const float4*)(ip + d);
    float ss = h.x*h.x + h.y*h.y + h.z*h.z + h.w*h.w;
    // reduce over 9 warps
    #pragma unroll
    for (int o = 16; o > 0; o >>= 1) ss += __shfl_down_sync(0xffffffffu, ss, o);
    __shared__ float red[9];
    int lane = threadIdx.x & 31, wid = threadIdx.x >> 5;
    if (lane == 0) red[wid] = ss;
    __syncthreads();
    if (threadIdx.x == 0) {
        float t = 0.f;
        #pragma unroll
        for (int i = 0; i < 9; i++) t += red[i];
        red[0] = rsqrtf(t * (1.0f/DIM) + 1e-6f);
    }
    __syncthreads();
    float r = red[0];
    const float* tb = temb + b*TEMB6;
    float4 sh, sc;
    {
        const float* s0 = sst + idx0*DIM + d;
        const float* t0 = tb  + idx0*DIM + d;
        const float* s1 = sst + (idx0+1)*DIM + d;
        const float* t1 = tb  + (idx0+1)*DIM + d;
        sh = make_float4(s0[0]+t0[0], s0[1]+t0[1], s0[2]+t0[2], s0[3]+t0[3]);
        sc = make_float4(s1[0]+t1[0], s1[1]+t1[1], s1[2]+t1[2], s1[3]+t1[3]);
    }
    float4 o;
    o.x = h.x*r*(1.f+sc.x) + sh.x;
    o.y = h.y*r*(1.f+sc.y) + sh.y;
    o.z = h.z*r*(1.f+sc.z) + sh.z;
    o.w = h.w*r*(1.f+sc.w) + sh.w;
    *(float4*)(out + (size_t)row*DIM + d) = o;
}

// ---------------- generic NT SGEMM with fused epilogues ----------------
// C[M,Ntot] = A[M,K] * Bw[Ntot,K]^T (+ epilogue)
// EPI: 0 relu(acc+bias), 1 acc+bias, 2 gate_msa*(acc+bias)+extra,
//      3 silu(acc+bias), 4 extra + gate_mlp*acc
#define GBM 128
#define GBN 128
#define GBK 16
template<int EPI>
__global__ void __launch_bounds__(256) gemm_nt(
    const float* __restrict__ A, const float* __restrict__ Bw,
    const float* __restrict__ bias, float* __restrict__ C,
    int K, int Ntot,
    const float* __restrict__ extra,
    const float* __restrict__ temb, const float* __restrict__ sst, int gidx)
{
    __shared__ float As[GBK][GBM+4];
    __shared__ float Bs[GBK][GBN+4];
    const int m0 = blockIdx.y * GBM;
    const int n0 = blockIdx.x * GBN;
    const int tid = threadIdx.x;
    const int tx = tid & 15, ty = tid >> 4;

    float acc[8][8];
    #pragma unroll
    for (int i = 0; i < 8; i++)
        #pragma unroll
        for (int j = 0; j < 8; j++) acc[i][j] = 0.f;

    const int ar = tid >> 2;          // 0..63
    const int ac = (tid & 3) * 4;     // 0,4,8,12
    const float* Ap = A  + (size_t)(m0 + ar) * K + ac;
    const float* Bp = Bw + (size_t)(n0 + ar) * K + ac;

    for (int kt = 0; kt < K; kt += GBK) {
        float4 a0 = *(const float4*)(Ap + kt);
        float4 a1 = *(const float4*)(Ap + (size_t)64*K + kt);
        float4 b0 = *(const float4*)(Bp + kt);
        float4 b1 = *(const float4*)(Bp + (size_t)64*K + kt);
        __syncthreads();
        As[ac+0][ar] = a0.x; As[ac+1][ar] = a0.y; As[ac+2][ar] = a0.z; As[ac+3][ar] = a0.w;
        As[ac+0][ar+64] = a1.x; As[ac+1][ar+64] = a1.y; As[ac+2][ar+64] = a1.z; As[ac+3][ar+64] = a1.w;
        Bs[ac+0][ar] = b0.x; Bs[ac+1][ar] = b0.y; Bs[ac+2][ar] = b0.z; Bs[ac+3][ar] = b0.w;
        Bs[ac+0][ar+64] = b1.x; Bs[ac+1][ar+64] = b1.y; Bs[ac+2][ar+64] = b1.z; Bs[ac+3][ar+64] = b1.w;
        __syncthreads();
        #pragma unroll
        for (int k = 0; k < GBK; k++) {
            float af[8], bf[8];
            #pragma unroll
            for (int i = 0; i < 8; i++) af[i] = As[k][ty*8 + i];
            #pragma unroll
            for (int j = 0; j < 8; j++) bf[j] = Bs[k][tx*8 + j];
            #pragma unroll
            for (int i = 0; i < 8; i++)
                #pragma unroll
                for (int j = 0; j < 8; j++) acc[i][j] += af[i]*bf[j];
        }
    }

    #pragma unroll
    for (int i = 0; i < 8; i++) {
        int m = m0 + ty*8 + i;
        int b = m >> 12;
        #pragma unroll
        for (int j = 0; j < 8; j++) {
            int n = n0 + tx*8 + j;
            float v = acc[i][j];
            if (EPI == 0) { v += bias[n]; v = v > 0.f ? v : 0.f; }
            else if (EPI == 1) { v += bias[n]; }
            else if (EPI == 2) {
                v += bias[n];
                float g = sst[gidx*DIM + n] + temb[b*TEMB6 + gidx*DIM + n];
                v = g * v + extra[(size_t)m*DIM + n];
            } else if (EPI == 3) {
                v += bias[n];
                v = v / (1.f + expf(-v));
            } else if (EPI == 4) {
                float g = sst[gidx*DIM + n] + temb[b*TEMB6 + gidx*DIM + n];
                v = extra[(size_t)m*DIM + n] + g * v;
            }
            C[(size_t)m*Ntot + n] = v;
        }
    }
}

// ---------------- kv = sum_n k ⊗ [v,1]  (split over 8 N-chunks) -------------
__global__ void __launch_bounds__(264) kv_kernel(
    const float* __restrict__ Kq, const float* __restrict__ Vq)
{
    int bh = blockIdx.x;             // 0..31
    int b = bh >> 4, h = bh & 15;
    int chunk = blockIdx.y;          // 0..7
    __shared__ float ks[8][72];
    __shared__ float vs[8][80];
    int tid = threadIdx.x;
    if (tid < 8*7) vs[tid/7][73 + tid%7] = 0.f;   // pad region once
    int d0 = (tid % 24) * 3;
    int e0 = (tid / 24) * 7;                      // 0..70
    float acc[3][7];
    #pragma unroll
    for (int i = 0; i < 3; i++)
        #pragma unroll
        for (int j = 0; j < 7; j++) acc[i][j] = 0.f;

    const float* kbase = Kq + (size_t)(b*NN)*DIM + h*HD;
    const float* vbase = Vq + (size_t)(b*NN)*DIM + h*HD;
    int nstart = chunk * 512;

    for (int nn = 0; nn < 512; nn += 8) {
        __syncthreads();
        for (int i = tid; i < 8*72; i += 264) {
            int r = i / 72, d = i - r*72;
            ks[r][d] = kbase[(size_t)(nstart+nn+r)*DIM + d];
        }
        for (int i = tid; i < 8*73; i += 264) {
            int r = i / 73, e = i - r*73;
            vs[r][e] = (e < 72) ? vbase[(size_t)(nstart+nn+r)*DIM + e] : 1.0f;
        }
        __syncthreads();
        #pragma unroll
        for (int r = 0; r < 8; r++) {
            float kk[3], vv[7];
            #pragma unroll
            for (int i = 0; i < 3; i++) kk[i] = ks[r][d0+i];
            #pragma unroll
            for (int j = 0; j < 7; j++) vv[j] = vs[r][e0+j];
            #pragma unroll
            for (int i = 0; i < 3; i++)
                #pragma unroll
                for (int j = 0; j < 7; j++) acc[i][j] += kk[i]*vv[j];
        }
    }
    float* outp = g_kvp + ((size_t)chunk * 32 + bh) * (HD*HDE);
    #pragma unroll
    for (int i = 0; i < 3; i++)
        #pragma unroll
        for (int j = 0; j < 7; j++) {
            int e = e0 + j;
            if (e < HDE) outp[(d0+i)*HDE + e] = acc[i][j];
        }
}

// deterministic tree-free fixed-order reduce of the 8 partials
__global__ void kv_reduce_kernel()
{
    int j = blockIdx.x * 256 + threadIdx.x;
    const int TOT = BB*HEADS*HD*HDE;       // 168192
    if (j >= TOT) return;
    float s = 0.f;
    #pragma unroll
    for (int c = 0; c < 8; c++) s += g_kvp[(size_t)c*TOT + j];
    g_kv[j] = s;
}

// ---------------- out = (q · kv), divide numerator by denominator ----------
__global__ void __launch_bounds__(320) attn_apply_kernel(
    const float* __restrict__ Q, float* __restrict__ attn)
{
    int bh = blockIdx.x;           // 0..31
    int b = bh >> 4, h = bh & 15;
    int n0 = blockIdx.y * 64;
    __shared__ float kvs[72][80];  // also reused as outs[64][80]
    __shared__ float qs[64][72];
    int tid = threadIdx.y * 80 + threadIdx.x;

    const float* kvsrc = g_kv + (size_t)bh * (HD*HDE);
    for (int i = tid; i < HD*HDE; i += 320) kvs[i/HDE][i%HDE] = kvsrc[i];
    const float* qbase = Q + (size_t)(b*NN + n0)*DIM + h*HD;
    for (int i = tid; i < 64*72; i += 320) {
        int r = i / 72, d = i - r*72;
        qs[r][d] = qbase[(size_t)r*DIM + d];
    }
    __syncthreads();

    int e = threadIdx.x, ty = threadIdx.y;
    float acc[16];
    #pragma unroll
    for (int r = 0; r < 16; r++) acc[r] = 0.f;
    if (e < HDE) {
        for (int d = 0; d < 72; d++) {
            float kvv = kvs[d][e];
            #pragma unroll
            for (int r = 0; r < 16; r++) acc[r] += qs[ty + r*4][d] * kvv;
        }
    }
    __syncthreads();            // done reading kvs; reuse as outs
    float* outs = &kvs[0][0];   // [64][80] view
    if (e < HDE) {
        #pragma unroll
        for (int r = 0; r < 16; r++) outs[(ty + r*4)*80 + e] = acc[r];
    }
    __syncthreads();
    float* ob = attn + (size_t)(b*NN + n0)*DIM + h*HD;
    for (int i = tid; i < 64*72; i += 320) {
        int r = i / 72, d = i - r*72;
        ob[(size_t)r*DIM + d] = outs[r*80 + d] / (outs[r*80 + 72] + 1e-15f);
    }
}

// ---------------- depthwise conv (k=3, pad 1) + GLU ----------------
__global__ void dwglu_kernel(const float* __restrict__ Y,
                             const float* __restrict__ Wdw,
                             const float* __restrict__ bdw,
                             float* __restrict__ Z)
{
    int idx = blockIdx.x * 256 + threadIdx.x;
    const int TOT = BB*NN*HID;
    if (idx >= TOT) return;
    int c = idx % HID;
    int n = (idx / HID) & (NN-1);
    int b = idx / (HID*NN);

    float xg = bdw[c];
    float gt = bdw[c + HID];
    #pragma unroll
    for (int t = 0; t < 3; t++) {
        int nn = n + t - 1;
        if (nn >= 0 && nn < NN) {
            const float* yr = Y + (size_t)(b*NN + nn) * HID2;
            xg += yr[c]        * Wdw[c*3 + t];
            gt += yr[c + HID]  * Wdw[(c + HID)*3 + t];
        }
    }
    float s = gt / (1.f + expf(-gt));
    Z[(size_t)idx] = xg * s;
}

// ---------------- host launcher ----------------
extern "C" void kernel_launch(void* const* d_in, const int* in_sizes, int n_in,
                              void* d_out, int out_size)
{
    const float* hidden = (const float*)d_in[0];
    const float* temb   = (const float*)d_in[1];
    const float* sst    = (const float*)d_in[2];
    const float* Wq     = (const float*)d_in[3];
    const float* bq     = (const float*)d_in[4];
    const float* Wk     = (const float*)d_in[5];
    const float* bk     = (const float*)d_in[6];
    const float* Wv     = (const float*)d_in[7];
    const float* bv     = (const float*)d_in[8];
    const float* Wo     = (const float*)d_in[9];
    const float* bo     = (const float*)d_in[10];
    const float* W_inv  = (const float*)d_in[11];
    const float* b_inv  = (const float*)d_in[12];
    const float* W_dw   = (const float*)d_in[13];
    const float* b_dw   = (const float*)d_in[14];
    const float* W_pt   = (const float*)d_in[15];
    float* out = (float*)d_out;

    float *x, *q, *k, *v, *attn, *h2, *y, *z;
    cudaGetSymbolAddress((void**)&x,    g_x);
    cudaGetSymbolAddress((void**)&q,    g_q);
    cudaGetSymbolAddress((void**)&k,    g_k);
    cudaGetSymbolAddress((void**)&v,    g_v);
    cudaGetSymbolAddress((void**)&attn, g_attn);
    cudaGetSymbolAddress((void**)&h2,   g_h2);
    cudaGetSymbolAddress((void**)&y,    g_y);
    cudaGetSymbolAddress((void**)&z,    g_z);

    dim3 gq(DIM/GBN, MM/GBM);        // (9, 64)

    // 1) x = rms(hidden)*(1+scale_msa)+shift_msa
    modrms_kernel<<<MM, 288>>>(hidden, temb, sst, x, 0);

    // 2) q,k,v projections
    gemm_nt<0><<<gq, 256>>>(x, Wq, bq, q, DIM, DIM, nullptr, nullptr, nullptr, 0);
    gemm_nt<0><<<gq, 256>>>(x, Wk, bk, k, DIM, DIM, nullptr, nullptr, nullptr, 0);
    gemm_nt<1><<<gq, 256>>>(x, Wv, bv, v, DIM, DIM, nullptr, nullptr, nullptr, 0);

    // 3) kv accumulation (split-K over 8 chunks) + fixed-order reduce
    kv_kernel<<<dim3(32, 8), 264>>>(k, v);
    kv_reduce_kernel<<<(BB*HEADS*HD*HDE + 255)/256, 256>>>();

    // 4) out = q·kv, numerator/denominator
    attn_apply_kernel<<<dim3(32, NN/64), dim3(80, 4)>>>(q, attn);

    // 5) h2 = gate_msa*(attn@Wo^T + bo) + hidden
    gemm_nt<2><<<gq, 256>>>(attn, Wo, bo, h2, DIM, DIM, hidden, temb, sst, 2);

    // 6) x = rms(h2)*(1+scale_mlp)+shift_mlp
    modrms_kernel<<<MM, 288>>>(h2, temb, sst, x, 3);

    // 7) y = silu(x@W_inv^T + b_inv)   (N=9216)
    gemm_nt<3><<<dim3(HID2/GBN, MM/GBM), 256>>>(x, W_inv, b_inv, y, DIM, HID2,
                                                nullptr, nullptr, nullptr, 0);

    // 8) depthwise conv + GLU -> z (B,N,HID)
    dwglu_kernel<<<(BB*NN*HID + 255)/256, 256>>>(y, W_dw, b_dw, z);

    // 9) out = h2 + gate_mlp*(z@W_pt^T)   (K=4608)
    gemm_nt<4><<<gq, 256>>>(z, W_pt, nullptr, out, HID, DIM, h2, temb, sst, 5);
}

// round 2
// speedup vs baseline: 2.8972x; 2.8972x over previous
#include <cuda_runtime.h>
#include <math.h>

#define DIM   1152
#define HEADS 16
#define HD    72
#define HDE   73
#define HID   4608
#define HID2  9216
#define BB    2
#define NN    4096
#define MM    (BB*NN)        // 8192
#define TEMB6 (6*DIM)

// ---------------- scratch (device globals; no allocation) ----------------
__device__ float g_x[MM*DIM];
__device__ float g_q[MM*DIM];
__device__ float g_k[MM*DIM];
__device__ float g_v[MM*DIM];
__device__ float g_attn[MM*DIM];
__device__ float g_h2[MM*DIM];
__device__ float g_y[(size_t)MM*HID2];
__device__ float g_z[(size_t)MM*HID];
__device__ float g_kvp[8*BB*HEADS*HD*HDE];
__device__ float g_kv[BB*HEADS*HD*HDE];
// tf32-rounded weights
__device__ float g_wq[DIM*DIM];
__device__ float g_wk[DIM*DIM];
__device__ float g_wv[DIM*DIM];
__device__ float g_wo[DIM*DIM];
__device__ float g_winv[2*HID*DIM];
__device__ float g_wpt[DIM*HID];

__device__ __forceinline__ float tf32r(float x) {
    float r;
    asm("cvt.rna.tf32.f32 %0, %1;" : "=f"(r) : "f"(x));
    return r;
}

// ---------------- tf32 round of weights ----------------
__global__ void cvt_tf32_kernel(const float4* __restrict__ src,
                                float4* __restrict__ dst, int n4)
{
    int i = blockIdx.x * 256 + threadIdx.x;
    if (i < n4) {
        float4 v = src[i];
        v.x = tf32r(v.x); v.y = tf32r(v.y); v.z = tf32r(v.z); v.w = tf32r(v.w);
        dst[i] = v;
    }
}

// ---------------- adaLN modulation + RMSNorm (output tf32-rounded) ---------
__global__ void __launch_bounds__(288) modrms_kernel(
    const float* __restrict__ in, const float* __restrict__ temb,
    const float* __restrict__ sst, float* __restrict__ out, int idx0)
{
    int row = blockIdx.x;
    int b   = row >> 12;
    const float* ip = in + (size_t)row*DIM;
    int d = threadIdx.x * 4;
    float4 h = *(const float4*)(ip + d);
    float ss = h.x*h.x + h.y*h.y + h.z*h.z + h.w*h.w;
    #pragma unroll
    for (int o = 16; o > 0; o >>= 1) ss += __shfl_down_sync(0xffffffffu, ss, o);
    __shared__ float red[9];
    int lane = threadIdx.x & 31, wid = threadIdx.x >> 5;
    if (lane == 0) red[wid] = ss;
    __syncthreads();
    if (threadIdx.x == 0) {
        float t = 0.f;
        #pragma unroll
        for (int i = 0; i < 9; i++) t += red[i];
        red[0] = rsqrtf(t * (1.0f/DIM) + 1e-6f);
    }
    __syncthreads();
    float r = red[0];
    const float* tb = temb + b*TEMB6;
    float4 sh, sc;
    {
        const float* s0 = sst + idx0*DIM + d;
        const float* t0 = tb  + idx0*DIM + d;
        const float* s1 = sst + (idx0+1)*DIM + d;
        const float* t1 = tb  + (idx0+1)*DIM + d;
        sh = make_float4(s0[0]+t0[0], s0[1]+t0[1], s0[2]+t0[2], s0[3]+t0[3]);
        sc = make_float4(s1[0]+t1[0], s1[1]+t1[1], s1[2]+t1[2], s1[3]+t1[3]);
    }
    float4 o;
    o.x = tf32r(h.x*r*(1.f+sc.x) + sh.x);
    o.y = tf32r(h.y*r*(1.f+sc.y) + sh.y);
    o.z = tf32r(h.z*r*(1.f+sc.z) + sh.z);
    o.w = tf32r(h.w*r*(1.f+sc.w) + sh.w);
    *(float4*)(out + (size_t)row*DIM + d) = o;
}

// ---------------- tf32 tensor-core NT GEMM with fused epilogues -------------
// C[M,Ntot] = A[M,K] * Bw[Ntot,K]^T (+ epilogue)
// EPI: 0 relu(acc+bias), 1 acc+bias, 2 gate_msa*(acc+bias)+extra,
//      3 silu(acc+bias), 4 extra + gate_mlp*acc
#define BM 128
#define BN 128
#define BKG 32
#define BKP 36

#define CP16(dst, src) \
    asm volatile("cp.async.cg.shared.global [%0], [%1], 16;" \
        :: "r"((unsigned)__cvta_generic_to_shared(dst)), "l"(src))

__device__ __forceinline__ void mma_tf32(float c[4], const unsigned a[4], const unsigned b[2]) {
    asm volatile(
        "mma.sync.aligned.m16n8k8.row.col.f32.tf32.tf32.f32 "
        "{%0,%1,%2,%3}, {%4,%5,%6,%7}, {%8,%9}, {%0,%1,%2,%3};\n"
        : "+f"(c[0]), "+f"(c[1]), "+f"(c[2]), "+f"(c[3])
        : "r"(a[0]), "r"(a[1]), "r"(a[2]), "r"(a[3]), "r"(b[0]), "r"(b[1]));
}

template<int EPI>
__global__ void __launch_bounds__(256, 2) gemm_tf32(
    const float* __restrict__ A, const float* __restrict__ Bw,
    const float* __restrict__ bias, float* __restrict__ C,
    int K, int Ntot,
    const float* __restrict__ extra,
    const float* __restrict__ temb, const float* __restrict__ sst, int gidx)
{
    extern __shared__ float sm[];
    float* Asm = sm;                    // [2][BM][BKP]
    float* Bsm = sm + 2*BM*BKP;         // [2][BN][BKP]

    const int m0 = blockIdx.y * BM, n0 = blockIdx.x * BN;
    const int tid = threadIdx.x;
    const int lane = tid & 31, warp = tid >> 5;
    const int wm = warp >> 2, wn = warp & 3;      // 2 x 4 warps, 64x32 per warp
    const int ar = tid >> 3;                      // 0..31
    const int ac = (tid & 7) * 4;                 // 0..28

    const float* Ap = A  + (size_t)(m0 + ar) * K + ac;
    const float* Bp = Bw + (size_t)(n0 + ar) * K + ac;

    float acc[4][4][4];
    #pragma unroll
    for (int i = 0; i < 4; i++)
        #pragma unroll
        for (int j = 0; j < 4; j++)
            #pragma unroll
            for (int q = 0; q < 4; q++) acc[i][j][q] = 0.f;

    const int KT = K / BKG;

    // stage 0
    {
        #pragma unroll
        for (int r = 0; r < 4; r++) {
            CP16(&Asm[0*BM*BKP + (ar + r*32)*BKP + ac], Ap + (size_t)r*32*K);
            CP16(&Bsm[0*BN*BKP + (ar + r*32)*BKP + ac], Bp + (size_t)r*32*K);
        }
        asm volatile("cp.async.commit_group;");
    }

    const int rr = lane >> 2, cc = lane & 3;

    for (int kt = 0; kt < KT; kt++) {
        int buf = kt & 1;
        if (kt + 1 < KT) {
            int nb = buf ^ 1;
            size_t off = (size_t)(kt + 1) * BKG;
            #pragma unroll
            for (int r = 0; r < 4; r++) {
                CP16(&Asm[nb*BM*BKP + (ar + r*32)*BKP + ac], Ap + (size_t)r*32*K + off);
                CP16(&Bsm[nb*BN*BKP + (ar + r*32)*BKP + ac], Bp + (size_t)r*32*K + off);
            }
            asm volatile("cp.async.commit_group;");
            asm volatile("cp.async.wait_group 1;");
        } else {
            asm volatile("cp.async.wait_group 0;");
        }
        __syncthreads();

        const float* Ab = Asm + buf*BM*BKP;
        const float* Bb = Bsm + buf*BN*BKP;
        #pragma unroll
        for (int ks = 0; ks < 4; ks++) {
            int k0 = ks * 8;
            unsigned a[4][4], b[4][2];
            #pragma unroll
            for (int mt = 0; mt < 4; mt++) {
                int rb = wm*64 + mt*16;
                a[mt][0] = __float_as_uint(Ab[(rb+rr  )*BKP + k0+cc  ]);
                a[mt][1] = __float_as_uint(Ab[(rb+rr+8)*BKP + k0+cc  ]);
                a[mt][2] = __float_as_uint(Ab[(rb+rr  )*BKP + k0+cc+4]);
                a[mt][3] = __float_as_uint(Ab[(rb+rr+8)*BKP + k0+cc+4]);
            }
            #pragma unroll
            for (int nt = 0; nt < 4; nt++) {
                int cb = wn*32 + nt*8;
                b[nt][0] = __float_as_uint(Bb[(cb+rr)*BKP + k0+cc  ]);
                b[nt][1] = __float_as_uint(Bb[(cb+rr)*BKP + k0+cc+4]);
            }
            #pragma unroll
            for (int mt = 0; mt < 4; mt++)
                #pragma unroll
                for (int nt = 0; nt < 4; nt++)
                    mma_tf32(acc[mt][nt], a[mt], b[nt]);
        }
        __syncthreads();
    }

    // epilogue
    #pragma unroll
    for (int mt = 0; mt < 4; mt++) {
        #pragma unroll
        for (int half = 0; half < 2; half++) {
            int m = m0 + wm*64 + mt*16 + rr + half*8;
            int bidx = m >> 12;
            #pragma unroll
            for (int nt = 0; nt < 4; nt++) {
                int n = n0 + wn*32 + nt*8 + cc*2;
                float v0 = acc[mt][nt][half*2+0];
                float v1 = acc[mt][nt][half*2+1];
                if (EPI == 0) {
                    v0 += bias[n];   v0 = v0 > 0.f ? v0 : 0.f;
                    v1 += bias[n+1]; v1 = v1 > 0.f ? v1 : 0.f;
                } else if (EPI == 1) {
                    v0 += bias[n]; v1 += bias[n+1];
                } else if (EPI == 2) {
                    v0 += bias[n]; v1 += bias[n+1];
                    float g0 = sst[gidx*DIM + n]   + temb[bidx*TEMB6 + gidx*DIM + n];
                    float g1 = sst[gidx*DIM + n+1] + temb[bidx*TEMB6 + gidx*DIM + n+1];
                    v0 = g0 * v0 + extra[(size_t)m*DIM + n];
                    v1 = g1 * v1 + extra[(size_t)m*DIM + n+1];
                } else if (EPI == 3) {
                    v0 += bias[n];   v0 = v0 / (1.f + expf(-v0));
                    v1 += bias[n+1]; v1 = v1 / (1.f + expf(-v1));
                } else if (EPI == 4) {
                    float g0 = sst[gidx*DIM + n]   + temb[bidx*TEMB6 + gidx*DIM + n];
                    float g1 = sst[gidx*DIM + n+1] + temb[bidx*TEMB6 + gidx*DIM + n+1];
                    v0 = extra[(size_t)m*DIM + n]   + g0 * v0;
                    v1 = extra[(size_t)m*DIM + n+1] + g1 * v1;
                }
                *(float2*)(C + (size_t)m*Ntot + n) = make_float2(v0, v1);
            }
        }
    }
}

// ---------------- kv = sum_n k (x) [v,1]  (split over 8 N-chunks) -----------
__global__ void __launch_bounds__(264) kv_kernel(
    const float* __restrict__ Kq, const float* __restrict__ Vq)
{
    int bh = blockIdx.x;
    int b = bh >> 4, h = bh & 15;
    int chunk = blockIdx.y;
    __shared__ float ks[8][72];
    __shared__ float vs[8][80];
    int tid = threadIdx.x;
    if (tid < 8*7) vs[tid/7][73 + tid%7] = 0.f;
    int d0 = (tid % 24) * 3;
    int e0 = (tid / 24) * 7;
    float acc[3][7];
    #pragma unroll
    for (int i = 0; i < 3; i++)
        #pragma unroll
        for (int j = 0; j < 7; j++) acc[i][j] = 0.f;

    const float* kbase = Kq + (size_t)(b*NN)*DIM + h*HD;
    const float* vbase = Vq + (size_t)(b*NN)*DIM + h*HD;
    int nstart = chunk * 512;

    for (int nn = 0; nn < 512; nn += 8) {
        __syncthreads();
        for (int i = tid; i < 8*72; i += 264) {
            int r = i / 72, d = i - r*72;
            ks[r][d] = kbase[(size_t)(nstart+nn+r)*DIM + d];
        }
        for (int i = tid; i < 8*73; i += 264) {
            int r = i / 73, e = i - r*73;
            vs[r][e] = (e < 72) ? vbase[(size_t)(nstart+nn+r)*DIM + e] : 1.0f;
        }
        __syncthreads();
        #pragma unroll
        for (int r = 0; r < 8; r++) {
            float kk[3], vv[7];
            #pragma unroll
            for (int i = 0; i < 3; i++) kk[i] = ks[r][d0+i];
            #pragma unroll
            for (int j = 0; j < 7; j++) vv[j] = vs[r][e0+j];
            #pragma unroll
            for (int i = 0; i < 3; i++)
                #pragma unroll
                for (int j = 0; j < 7; j++) acc[i][j] += kk[i]*vv[j];
        }
    }
    float* outp = g_kvp + ((size_t)chunk * 32 + bh) * (HD*HDE);
    #pragma unroll
    for (int i = 0; i < 3; i++)
        #pragma unroll
        for (int j = 0; j < 7; j++) {
            int e = e0 + j;
            if (e < HDE) outp[(d0+i)*HDE + e] = acc[i][j];
        }
}

__global__ void kv_reduce_kernel()
{
    int j = blockIdx.x * 256 + threadIdx.x;
    const int TOT = BB*HEADS*HD*HDE;
    if (j >= TOT) return;
    float s = 0.f;
    #pragma unroll
    for (int c = 0; c < 8; c++) s += g_kvp[(size_t)c*TOT + j];
    g_kv[j] = s;
}

// ---------------- out = (q . kv), numerator/denominator, tf32-rounded -------
__global__ void __launch_bounds__(320) attn_apply_kernel(
    const float* __restrict__ Q, float* __restrict__ attn)
{
    int bh = blockIdx.x;
    int b = bh >> 4, h = bh & 15;
    int n0 = blockIdx.y * 64;
    __shared__ float kvs[72][80];
    __shared__ float qs[64][72];
    int tid = threadIdx.y * 80 + threadIdx.x;

    const float* kvsrc = g_kv + (size_t)bh * (HD*HDE);
    for (int i = tid; i < HD*HDE; i += 320) kvs[i/HDE][i%HDE] = kvsrc[i];
    const float* qbase = Q + (size_t)(b*NN + n0)*DIM + h*HD;
    for (int i = tid; i < 64*72; i += 320) {
        int r = i / 72, d = i - r*72;
        qs[r][d] = qbase[(size_t)r*DIM + d];
    }
    __syncthreads();

    int e = threadIdx.x, ty = threadIdx.y;
    float acc[16];
    #pragma unroll
    for (int r = 0; r < 16; r++) acc[r] = 0.f;
    if (e < HDE) {
        for (int d = 0; d < 72; d++) {
            float kvv = kvs[d][e];
            #pragma unroll
            for (int r = 0; r < 16; r++) acc[r] += qs[ty + r*4][d] * kvv;
        }
    }
    __syncthreads();
    float* outs = &kvs[0][0];
    if (e < HDE) {
        #pragma unroll
        for (int r = 0; r < 16; r++) outs[(ty + r*4)*80 + e] = acc[r];
    }
    __syncthreads();
    float* ob = attn + (size_t)(b*NN + n0)*DIM + h*HD;
    for (int i = tid; i < 64*72; i += 320) {
        int r = i / 72, d = i - r*72;
        ob[(size_t)r*DIM + d] = tf32r(outs[r*80 + d] / (outs[r*80 + 72] + 1e-15f));
    }
}

// ---------------- depthwise conv (k=3, pad 1) + GLU, tf32-rounded -----------
__global__ void dwglu_kernel(const float* __restrict__ Y,
                             const float* __restrict__ Wdw,
                             const float* __restrict__ bdw,
                             float* __restrict__ Z)
{
    int idx = blockIdx.x * 256 + threadIdx.x;
    const int TOT = BB*NN*HID;
    if (idx >= TOT) return;
    int c = idx % HID;
    int n = (idx / HID) & (NN-1);
    int b = idx / (HID*NN);

    float xg = bdw[c];
    float gt = bdw[c + HID];
    #pragma unroll
    for (int t = 0; t < 3; t++) {
        int nn = n + t - 1;
        if (nn >= 0 && nn < NN) {
            const float* yr = Y + (size_t)(b*NN + nn) * HID2;
            xg += yr[c]        * Wdw[c*3 + t];
            gt += yr[c + HID]  * Wdw[(c + HID)*3 + t];
        }
    }
    float s = gt / (1.f + expf(-gt));
    Z[(size_t)idx] = tf32r(xg * s);
}

// ---------------- host launcher ----------------
extern "C" void kernel_launch(void* const* d_in, const int* in_sizes, int n_in,
                              void* d_out, int out_size)
{
    const float* hidden = (const float*)d_in[0];
    const float* temb   = (const float*)d_in[1];
    const float* sst    = (const float*)d_in[2];
    const float* Wq     = (const float*)d_in[3];
    const float* bq     = (const float*)d_in[4];
    const float* Wk     = (const float*)d_in[5];
    const float* bk     = (const float*)d_in[6];
    const float* Wv     = (const float*)d_in[7];
    const float* bv     = (const float*)d_in[8];
    const float* Wo     = (const float*)d_in[9];
    const float* bo     = (const float*)d_in[10];
    const float* W_inv  = (const float*)d_in[11];
    const float* b_inv  = (const float*)d_in[12];
    const float* W_dw   = (const float*)d_in[13];
    const float* b_dw   = (const float*)d_in[14];
    const float* W_pt   = (const float*)d_in[15];
    float* out = (float*)d_out;

    float *x, *q, *k, *v, *attn, *h2, *y, *z;
    float *wq, *wk, *wv, *wo, *winv, *wpt;
    cudaGetSymbolAddress((void**)&x,    g_x);
    cudaGetSymbolAddress((void**)&q,    g_q);
    cudaGetSymbolAddress((void**)&k,    g_k);
    cudaGetSymbolAddress((void**)&v,    g_v);
    cudaGetSymbolAddress((void**)&attn, g_attn);
    cudaGetSymbolAddress((void**)&h2,   g_h2);
    cudaGetSymbolAddress((void**)&y,    g_y);
    cudaGetSymbolAddress((void**)&z,    g_z);
    cudaGetSymbolAddress((void**)&wq,   g_wq);
    cudaGetSymbolAddress((void**)&wk,   g_wk);
    cudaGetSymbolAddress((void**)&wv,   g_wv);
    cudaGetSymbolAddress((void**)&wo,   g_wo);
    cudaGetSymbolAddress((void**)&winv, g_winv);
    cudaGetSymbolAddress((void**)&wpt,  g_wpt);

    const int SMEM = 2*(2*BM*BKP)*4*  1  +  2*(BN*BKP)*4*2; // = 2*(As+Bs) bytes
    // (explicit: As 2*128*36*4 = 36864, Bs same -> 73728)
    const int SMEM_BYTES = 2*BM*BKP*4 + 2*BN*BKP*4;
    (void)SMEM;
    cudaFuncSetAttribute(gemm_tf32<0>, cudaFuncAttributeMaxDynamicSharedMemorySize, SMEM_BYTES);
    cudaFuncSetAttribute(gemm_tf32<1>, cudaFuncAttributeMaxDynamicSharedMemorySize, SMEM_BYTES);
    cudaFuncSetAttribute(gemm_tf32<2>, cudaFuncAttributeMaxDynamicSharedMemorySize, SMEM_BYTES);
    cudaFuncSetAttribute(gemm_tf32<3>, cudaFuncAttributeMaxDynamicSharedMemorySize, SMEM_BYTES);
    cudaFuncSetAttribute(gemm_tf32<4>, cudaFuncAttributeMaxDynamicSharedMemorySize, SMEM_BYTES);

    // 0) round weights to tf32 once per call
    cvt_tf32_kernel<<<(DIM*DIM/4 + 255)/256, 256>>>((const float4*)Wq, (float4*)wq, DIM*DIM/4);
    cvt_tf32_kernel<<<(DIM*DIM/4 + 255)/256, 256>>>((const float4*)Wk, (float4*)wk, DIM*DIM/4);
    cvt_tf32_kernel<<<(DIM*DIM/4 + 255)/256, 256>>>((const float4*)Wv, (float4*)wv, DIM*DIM/4);
    cvt_tf32_kernel<<<(DIM*DIM/4 + 255)/256, 256>>>((const float4*)Wo, (float4*)wo, DIM*DIM/4);
    cvt_tf32_kernel<<<(2*HID*DIM/4 + 255)/256, 256>>>((const float4*)W_inv, (float4*)winv, 2*HID*DIM/4);
    cvt_tf32_kernel<<<(DIM*HID/4 + 255)/256, 256>>>((const float4*)W_pt, (float4*)wpt, DIM*HID/4);

    dim3 gq(DIM/BN, MM/BM);          // (9, 64)

    // 1) x = rms(hidden)*(1+scale_msa)+shift_msa  (tf32-rounded)
    modrms_kernel<<<MM, 288>>>(hidden, temb, sst, x, 0);

    // 2) q,k,v projections (tensor cores)
    gemm_tf32<0><<<gq, 256, SMEM_BYTES>>>(x, wq, bq, q, DIM, DIM, nullptr, nullptr, nullptr, 0);
    gemm_tf32<0><<<gq, 256, SMEM_BYTES>>>(x, wk, bk, k, DIM, DIM, nullptr, nullptr, nullptr, 0);
    gemm_tf32<1><<<gq, 256, SMEM_BYTES>>>(x, wv, bv, v, DIM, DIM, nullptr, nullptr, nullptr, 0);

    // 3) kv accumulation + deterministic reduce
    kv_kernel<<<dim3(32, 8), 264>>>(k, v);
    kv_reduce_kernel<<<(BB*HEADS*HD*HDE + 255)/256, 256>>>();

    // 4) out = q.kv, numerator/denominator
    attn_apply_kernel<<<dim3(32, NN/64), dim3(80, 4)>>>(q, attn);

    // 5) h2 = gate_msa*(attn@Wo^T + bo) + hidden
    gemm_tf32<2><<<gq, 256, SMEM_BYTES>>>(attn, wo, bo, h2, DIM, DIM, hidden, temb, sst, 2);

    // 6) x = rms(h2)*(1+scale_mlp)+shift_mlp
    modrms_kernel<<<MM, 288>>>(h2, temb, sst, x, 3);

    // 7) y = silu(x@W_inv^T + b_inv)
    gemm_tf32<3><<<dim3(HID2/BN, MM/BM), 256, SMEM_BYTES>>>(x, winv, b_inv, y, DIM, HID2,
                                                            nullptr, nullptr, nullptr, 0);

    // 8) depthwise conv + GLU -> z
    dwglu_kernel<<<(BB*NN*HID + 255)/256, 256>>>(y, W_dw, b_dw, z);

    // 9) out = h2 + gate_mlp*(z@W_pt^T)
    gemm_tf32<4><<<gq, 256, SMEM_BYTES>>>(z, wpt, nullptr, out, HID, DIM, h2, temb, sst, 5);
}

// round 3
// speedup vs baseline: 4.2882x; 1.4801x over previous
#include <cuda_runtime.h>
#include <cuda_fp16.h>
#include <math.h>

#define DIM   1152
#define HEADS 16
#define HD    72
#define HDE   73
#define HID   4608
#define HID2  9216
#define BB    2
#define NN    4096
#define MM    (BB*NN)        // 8192
#define TEMB6 (6*DIM)

// ---------------- scratch (device globals; no allocation) ----------------
__device__ __half g_xh[MM*DIM];          // modulated input (half, GEMM A operand)
__device__ float  g_q[MM*DIM];
__device__ float  g_k[MM*DIM];
__device__ float  g_v[MM*DIM];
__device__ __half g_attnh[MM*DIM];       // attention out (half, GEMM A operand)
__device__ float  g_h2[MM*DIM];
__device__ __half g_yh[(size_t)MM*HID2]; // inverted conv out (half)
__device__ __half g_zh[(size_t)MM*HID];  // dwconv+GLU out (half)
__device__ float  g_kvp[8*BB*HEADS*HD*HDE];
__device__ float  g_kv[BB*HEADS*HD*HDE];
// half weights
__device__ __half g_wq[DIM*DIM];
__device__ __half g_wk[DIM*DIM];
__device__ __half g_wv[DIM*DIM];
__device__ __half g_wo[DIM*DIM];
__device__ __half g_winv[2*HID*DIM];
__device__ __half g_wpt[DIM*HID];

// ---------------- fp32 -> half weight conversion ----------------
__global__ void cvt_half_kernel(const float4* __restrict__ src,
                                __half* __restrict__ dst, int n4)
{
    int i = blockIdx.x * 256 + threadIdx.x;
    if (i < n4) {
        float4 v = src[i];
        __half2 lo = __floats2half2_rn(v.x, v.y);
        __half2 hi = __floats2half2_rn(v.z, v.w);
        *(uint2*)(dst + (size_t)i*4) = make_uint2(
            *(unsigned*)&lo, *(unsigned*)&hi);
    }
}

// ---------------- adaLN modulation + RMSNorm -> half ----------------
__global__ void __launch_bounds__(288) modrms_kernel(
    const float* __restrict__ in, const float* __restrict__ temb,
    const float* __restrict__ sst, __half* __restrict__ out, int idx0)
{
    int row = blockIdx.x;
    int b   = row >> 12;
    const float* ip = in + (size_t)row*DIM;
    int d = threadIdx.x * 4;
    float4 h = *(const float4*)(ip + d);
    float ss = h.x*h.x + h.y*h.y + h.z*h.z + h.w*h.w;
    #pragma unroll
    for (int o = 16; o > 0; o >>= 1) ss += __shfl_down_sync(0xffffffffu, ss, o);
    __shared__ float red[9];
    int lane = threadIdx.x & 31, wid = threadIdx.x >> 5;
    if (lane == 0) red[wid] = ss;
    __syncthreads();
    if (threadIdx.x == 0) {
        float t = 0.f;
        #pragma unroll
        for (int i = 0; i < 9; i++) t += red[i];
        red[0] = rsqrtf(t * (1.0f/DIM) + 1e-6f);
    }
    __syncthreads();
    float r = red[0];
    const float* tb = temb + b*TEMB6;
    float4 sh, sc;
    {
        const float* s0 = sst + idx0*DIM + d;
        const float* t0 = tb  + idx0*DIM + d;
        const float* s1 = sst + (idx0+1)*DIM + d;
        const float* t1 = tb  + (idx0+1)*DIM + d;
        sh = make_float4(s0[0]+t0[0], s0[1]+t0[1], s0[2]+t0[2], s0[3]+t0[3]);
        sc = make_float4(s1[0]+t1[0], s1[1]+t1[1], s1[2]+t1[2], s1[3]+t1[3]);
    }
    __half2 o0 = __floats2half2_rn(h.x*r*(1.f+sc.x) + sh.x,
                                   h.y*r*(1.f+sc.y) + sh.y);
    __half2 o1 = __floats2half2_rn(h.z*r*(1.f+sc.z) + sh.z,
                                   h.w*r*(1.f+sc.w) + sh.w);
    *(uint2*)(out + (size_t)row*DIM + d) = make_uint2(
        *(unsigned*)&o0, *(unsigned*)&o1);
}

// ---------------- fp16 tensor-core NT GEMM with fused epilogues -------------
// C[M,Ntot] = A[M,K](half) * Bw[Ntot,K](half)^T (+ epilogue), fp32 accum
// EPI: 0 relu(acc+bias)->f32, 1 acc+bias->f32, 2 gate_msa*(acc+bias)+extra->f32,
//      3 silu(acc+bias)->half, 4 extra + gate_mlp*acc->f32
#define BM 128
#define BN 128
#define BKG 32
#define BKP 40   // half elems per smem row (32 + 8 pad); 80B row, 16B-aligned

#define CP16(dst, src) \
    asm volatile("cp.async.cg.shared.global [%0], [%1], 16;" \
        :: "r"((unsigned)__cvta_generic_to_shared(dst)), "l"(src))

__device__ __forceinline__ void mma_f16(float c[4], const unsigned a[4], const unsigned b[2]) {
    asm volatile(
        "mma.sync.aligned.m16n8k16.row.col.f32.f16.f16.f32 "
        "{%0,%1,%2,%3}, {%4,%5,%6,%7}, {%8,%9}, {%0,%1,%2,%3};\n"
        : "+f"(c[0]), "+f"(c[1]), "+f"(c[2]), "+f"(c[3])
        : "r"(a[0]), "r"(a[1]), "r"(a[2]), "r"(a[3]), "r"(b[0]), "r"(b[1]));
}

template<int EPI, typename OutT>
__global__ void __launch_bounds__(256, 2) gemm_f16(
    const __half* __restrict__ A, const __half* __restrict__ Bw,
    const float* __restrict__ bias, OutT* __restrict__ C,
    int K, int Ntot,
    const float* __restrict__ extra,
    const float* __restrict__ temb, const float* __restrict__ sst, int gidx)
{
    __shared__ __half Asm[2][BM][BKP];
    __shared__ __half Bsm[2][BN][BKP];

    const int m0 = blockIdx.y * BM, n0 = blockIdx.x * BN;
    const int tid = threadIdx.x;
    const int lane = tid & 31, warp = tid >> 5;
    const int wm = warp >> 2, wn = warp & 3;      // 2 x 4 warps -> 64x32 per warp
    const int ar = tid >> 2;                      // 0..63
    const int ac = (tid & 3) * 8;                 // 0,8,16,24 (halfs)

    const __half* Ap = A  + (size_t)(m0 + ar) * K + ac;
    const __half* Bp = Bw + (size_t)(n0 + ar) * K + ac;

    float acc[4][4][4];
    #pragma unroll
    for (int i = 0; i < 4; i++)
        #pragma unroll
        for (int j = 0; j < 4; j++)
            #pragma unroll
            for (int q = 0; q < 4; q++) acc[i][j][q] = 0.f;

    const int KT = K / BKG;

    // stage 0
    {
        #pragma unroll
        for (int r = 0; r < 2; r++) {
            CP16(&Asm[0][ar + r*64][ac], Ap + (size_t)r*64*K);
            CP16(&Bsm[0][ar + r*64][ac], Bp + (size_t)r*64*K);
        }
        asm volatile("cp.async.commit_group;");
    }

    const int rr = lane >> 2, cc = lane & 3;

    for (int kt = 0; kt < KT; kt++) {
        int buf = kt & 1;
        if (kt + 1 < KT) {
            int nb = buf ^ 1;
            size_t off = (size_t)(kt + 1) * BKG;
            #pragma unroll
            for (int r = 0; r < 2; r++) {
                CP16(&Asm[nb][ar + r*64][ac], Ap + (size_t)r*64*K + off);
                CP16(&Bsm[nb][ar + r*64][ac], Bp + (size_t)r*64*K + off);
            }
            asm volatile("cp.async.commit_group;");
            asm volatile("cp.async.wait_group 1;");
        } else {
            asm volatile("cp.async.wait_group 0;");
        }
        __syncthreads();

        #pragma unroll
        for (int ks = 0; ks < 2; ks++) {
            int k0 = ks * 16;
            unsigned a[4][4], b[4][2];
            #pragma unroll
            for (int mt = 0; mt < 4; mt++) {
                int rb = wm*64 + mt*16;
                a[mt][0] = *(const unsigned*)&Asm[buf][rb+rr  ][k0 + cc*2    ];
                a[mt][1] = *(const unsigned*)&Asm[buf][rb+rr+8][k0 + cc*2    ];
                a[mt][2] = *(const unsigned*)&Asm[buf][rb+rr  ][k0 + cc*2 + 8];
                a[mt][3] = *(const unsigned*)&Asm[buf][rb+rr+8][k0 + cc*2 + 8];
            }
            #pragma unroll
            for (int nt = 0; nt < 4; nt++) {
                int cb = wn*32 + nt*8;
                b[nt][0] = *(const unsigned*)&Bsm[buf][cb+rr][k0 + cc*2    ];
                b[nt][1] = *(const unsigned*)&Bsm[buf][cb+rr][k0 + cc*2 + 8];
            }
            #pragma unroll
            for (int mt = 0; mt < 4; mt++)
                #pragma unroll
                for (int nt = 0; nt < 4; nt++)
                    mma_f16(acc[mt][nt], a[mt], b[nt]);
        }
        __syncthreads();
    }

    // epilogue
    #pragma unroll
    for (int mt = 0; mt < 4; mt++) {
        #pragma unroll
        for (int half_ = 0; half_ < 2; half_++) {
            int m = m0 + wm*64 + mt*16 + rr + half_*8;
            int bidx = m >> 12;
            #pragma unroll
            for (int nt = 0; nt < 4; nt++) {
                int n = n0 + wn*32 + nt*8 + cc*2;
                float v0 = acc[mt][nt][half_*2+0];
                float v1 = acc[mt][nt][half_*2+1];
                if (EPI == 0) {
                    v0 += bias[n];   v0 = v0 > 0.f ? v0 : 0.f;
                    v1 += bias[n+1]; v1 = v1 > 0.f ? v1 : 0.f;
                } else if (EPI == 1) {
                    v0 += bias[n]; v1 += bias[n+1];
                } else if (EPI == 2) {
                    v0 += bias[n]; v1 += bias[n+1];
                    float g0 = sst[gidx*DIM + n]   + temb[bidx*TEMB6 + gidx*DIM + n];
                    float g1 = sst[gidx*DIM + n+1] + temb[bidx*TEMB6 + gidx*DIM + n+1];
                    v0 = g0 * v0 + extra[(size_t)m*DIM + n];
                    v1 = g1 * v1 + extra[(size_t)m*DIM + n+1];
                } else if (EPI == 3) {
                    v0 += bias[n];   v0 = v0 / (1.f + expf(-v0));
                    v1 += bias[n+1]; v1 = v1 / (1.f + expf(-v1));
                } else if (EPI == 4) {
                    float g0 = sst[gidx*DIM + n]   + temb[bidx*TEMB6 + gidx*DIM + n];
                    float g1 = sst[gidx*DIM + n+1] + temb[bidx*TEMB6 + gidx*DIM + n+1];
                    v0 = extra[(size_t)m*DIM + n]   + g0 * v0;
                    v1 = extra[(size_t)m*DIM + n+1] + g1 * v1;
                }
                if (sizeof(OutT) == 4) {
                    *(float2*)((float*)C + (size_t)m*Ntot + n) = make_float2(v0, v1);
                } else {
                    __half2 hv = __floats2half2_rn(v0, v1);
                    *(unsigned*)((__half*)C + (size_t)m*Ntot + n) = *(unsigned*)&hv;
                }
            }
        }
    }
}

// ---------------- kv = sum_n k (x) [v,1]  (split over 8 N-chunks) -----------
__global__ void __launch_bounds__(264) kv_kernel(
    const float* __restrict__ Kq, const float* __restrict__ Vq)
{
    int bh = blockIdx.x;
    int b = bh >> 4, h = bh & 15;
    int chunk = blockIdx.y;
    __shared__ float ks[8][72];
    __shared__ float vs[8][80];
    int tid = threadIdx.x;
    if (tid < 8*7) vs[tid/7][73 + tid%7] = 0.f;
    int d0 = (tid % 24) * 3;
    int e0 = (tid / 24) * 7;
    float acc[3][7];
    #pragma unroll
    for (int i = 0; i < 3; i++)
        #pragma unroll
        for (int j = 0; j < 7; j++) acc[i][j] = 0.f;

    const float* kbase = Kq + (size_t)(b*NN)*DIM + h*HD;
    const float* vbase = Vq + (size_t)(b*NN)*DIM + h*HD;
    int nstart = chunk * 512;

    for (int nn = 0; nn < 512; nn += 8) {
        __syncthreads();
        for (int i = tid; i < 8*72; i += 264) {
            int r = i / 72, d = i - r*72;
            ks[r][d] = kbase[(size_t)(nstart+nn+r)*DIM + d];
        }
        for (int i = tid; i < 8*73; i += 264) {
            int r = i / 73, e = i - r*73;
            vs[r][e] = (e < 72) ? vbase[(size_t)(nstart+nn+r)*DIM + e] : 1.0f;
        }
        __syncthreads();
        #pragma unroll
        for (int r = 0; r < 8; r++) {
            float kk[3], vv[7];
            #pragma unroll
            for (int i = 0; i < 3; i++) kk[i] = ks[r][d0+i];
            #pragma unroll
            for (int j = 0; j < 7; j++) vv[j] = vs[r][e0+j];
            #pragma unroll
            for (int i = 0; i < 3; i++)
                #pragma unroll
                for (int j = 0; j < 7; j++) acc[i][j] += kk[i]*vv[j];
        }
    }
    float* outp = g_kvp + ((size_t)chunk * 32 + bh) * (HD*HDE);
    #pragma unroll
    for (int i = 0; i < 3; i++)
        #pragma unroll
        for (int j = 0; j < 7; j++) {
            int e = e0 + j;
            if (e < HDE) outp[(d0+i)*HDE + e] = acc[i][j];
        }
}

__global__ void kv_reduce_kernel()
{
    int j = blockIdx.x * 256 + threadIdx.x;
    const int TOT = BB*HEADS*HD*HDE;
    if (j >= TOT) return;
    float s = 0.f;
    #pragma unroll
    for (int c = 0; c < 8; c++) s += g_kvp[(size_t)c*TOT + j];
    g_kv[j] = s;
}

// ---------------- out = (q . kv), numerator/denominator -> half -------------
__global__ void __launch_bounds__(320) attn_apply_kernel(
    const float* __restrict__ Q, __half* __restrict__ attn)
{
    int bh = blockIdx.x;
    int b = bh >> 4, h = bh & 15;
    int n0 = blockIdx.y * 64;
    __shared__ float kvs[72][80];
    __shared__ float qs[64][72];
    int tid = threadIdx.y * 80 + threadIdx.x;

    const float* kvsrc = g_kv + (size_t)bh * (HD*HDE);
    for (int i = tid; i < HD*HDE; i += 320) kvs[i/HDE][i%HDE] = kvsrc[i];
    const float* qbase = Q + (size_t)(b*NN + n0)*DIM + h*HD;
    for (int i = tid; i < 64*72; i += 320) {
        int r = i / 72, d = i - r*72;
        qs[r][d] = qbase[(size_t)r*DIM + d];
    }
    __syncthreads();

    int e = threadIdx.x, ty = threadIdx.y;
    float acc[16];
    #pragma unroll
    for (int r = 0; r < 16; r++) acc[r] = 0.f;
    if (e < HDE) {
        for (int d = 0; d < 72; d++) {
            float kvv = kvs[d][e];
            #pragma unroll
            for (int r = 0; r < 16; r++) acc[r] += qs[ty + r*4][d] * kvv;
        }
    }
    __syncthreads();
    float* outs = &kvs[0][0];
    if (e < HDE) {
        #pragma unroll
        for (int r = 0; r < 16; r++) outs[(ty + r*4)*80 + e] = acc[r];
    }
    __syncthreads();
    __half* ob = attn + (size_t)(b*NN + n0)*DIM + h*HD;
    for (int i = tid; i < 64*72; i += 320) {
        int r = i / 72, d = i - r*72;
        ob[(size_t)r*DIM + d] = __float2half_rn(
            outs[r*80 + d] / (outs[r*80 + 72] + 1e-15f));
    }
}

// ---------------- depthwise conv (k=3, pad 1) + GLU (half in/out) -----------
__global__ void dwglu_kernel(const __half* __restrict__ Y,
                             const float* __restrict__ Wdw,
                             const float* __restrict__ bdw,
                             __half* __restrict__ Z)
{
    int idx = blockIdx.x * 256 + threadIdx.x;
    const int TOT = BB*NN*HID;
    if (idx >= TOT) return;
    int c = idx % HID;
    int n = (idx / HID) & (NN-1);
    int b = idx / (HID*NN);

    float xg = bdw[c];
    float gt = bdw[c + HID];
    #pragma unroll
    for (int t = 0; t < 3; t++) {
        int nn = n + t - 1;
        if (nn >= 0 && nn < NN) {
            const __half* yr = Y + (size_t)(b*NN + nn) * HID2;
            xg += __half2float(yr[c])       * Wdw[c*3 + t];
            gt += __half2float(yr[c + HID]) * Wdw[(c + HID)*3 + t];
        }
    }
    float s = gt / (1.f + expf(-gt));
    Z[(size_t)idx] = __float2half_rn(xg * s);
}

// ---------------- host launcher ----------------
extern "C" void kernel_launch(void* const* d_in, const int* in_sizes, int n_in,
                              void* d_out, int out_size)
{
    const float* hidden = (const float*)d_in[0];
    const float* temb   = (const float*)d_in[1];
    const float* sst    = (const float*)d_in[2];
    const float* Wq     = (const float*)d_in[3];
    const float* bq     = (const float*)d_in[4];
    const float* Wk     = (const float*)d_in[5];
    const float* bk     = (const float*)d_in[6];
    const float* Wv     = (const float*)d_in[7];
    const float* bv     = (const float*)d_in[8];
    const float* Wo     = (const float*)d_in[9];
    const float* bo     = (const float*)d_in[10];
    const float* W_inv  = (const float*)d_in[11];
    const float* b_inv  = (const float*)d_in[12];
    const float* W_dw   = (const float*)d_in[13];
    const float* b_dw   = (const float*)d_in[14];
    const float* W_pt   = (const float*)d_in[15];
    float* out = (float*)d_out;

    __half *xh, *attnh, *yh, *zh, *wq, *wk, *wv, *wo, *winv, *wpt;
    float *q, *k, *v, *h2;
    cudaGetSymbolAddress((void**)&xh,    g_xh);
    cudaGetSymbolAddress((void**)&q,     g_q);
    cudaGetSymbolAddress((void**)&k,     g_k);
    cudaGetSymbolAddress((void**)&v,     g_v);
    cudaGetSymbolAddress((void**)&attnh, g_attnh);
    cudaGetSymbolAddress((void**)&h2,    g_h2);
    cudaGetSymbolAddress((void**)&yh,    g_yh);
    cudaGetSymbolAddress((void**)&zh,    g_zh);
    cudaGetSymbolAddress((void**)&wq,    g_wq);
    cudaGetSymbolAddress((void**)&wk,    g_wk);
    cudaGetSymbolAddress((void**)&wv,    g_wv);
    cudaGetSymbolAddress((void**)&wo,    g_wo);
    cudaGetSymbolAddress((void**)&winv,  g_winv);
    cudaGetSymbolAddress((void**)&wpt,   g_wpt);

    // 0) convert weights to half
    cvt_half_kernel<<<(DIM*DIM/4 + 255)/256, 256>>>((const float4*)Wq, wq, DIM*DIM/4);
    cvt_half_kernel<<<(DIM*DIM/4 + 255)/256, 256>>>((const float4*)Wk, wk, DIM*DIM/4);
    cvt_half_kernel<<<(DIM*DIM/4 + 255)/256, 256>>>((const float4*)Wv, wv, DIM*DIM/4);
    cvt_half_kernel<<<(DIM*DIM/4 + 255)/256, 256>>>((const float4*)Wo, wo, DIM*DIM/4);
    cvt_half_kernel<<<(2*HID*DIM/4 + 255)/256, 256>>>((const float4*)W_inv, winv, 2*HID*DIM/4);
    cvt_half_kernel<<<(DIM*HID/4 + 255)/256, 256>>>((const float4*)W_pt, wpt, DIM*HID/4);

    dim3 gq(DIM/BN, MM/BM);          // (9, 64)

    // 1) x = rms(hidden)*(1+scale_msa)+shift_msa  -> half
    modrms_kernel<<<MM, 288>>>(hidden, temb, sst, xh, 0);

    // 2) q,k,v projections (fp16 tensor cores, fp32 out)
    gemm_f16<0,float><<<gq, 256>>>(xh, wq, bq, q, DIM, DIM, nullptr, nullptr, nullptr, 0);
    gemm_f16<0,float><<<gq, 256>>>(xh, wk, bk, k, DIM, DIM, nullptr, nullptr, nullptr, 0);
    gemm_f16<1,float><<<gq, 256>>>(xh, wv, bv, v, DIM, DIM, nullptr, nullptr, nullptr, 0);

    // 3) kv accumulation + deterministic reduce
    kv_kernel<<<dim3(32, 8), 264>>>(k, v);
    kv_reduce_kernel<<<(BB*HEADS*HD*HDE + 255)/256, 256>>>();

    // 4) out = q.kv, numerator/denominator -> half
    attn_apply_kernel<<<dim3(32, NN/64), dim3(80, 4)>>>(q, attnh);

    // 5) h2 = gate_msa*(attn@Wo^T + bo) + hidden -> f32
    gemm_f16<2,float><<<gq, 256>>>(attnh, wo, bo, h2, DIM, DIM, hidden, temb, sst, 2);

    // 6) x = rms(h2)*(1+scale_mlp)+shift_mlp -> half
    modrms_kernel<<<MM, 288>>>(h2, temb, sst, xh, 3);

    // 7) y = silu(x@W_inv^T + b_inv) -> half
    gemm_f16<3,__half><<<dim3(HID2/BN, MM/BM), 256>>>(xh, winv, b_inv, yh, DIM, HID2,
                                                      nullptr, nullptr, nullptr, 0);

    // 8) depthwise conv + GLU -> half z
    dwglu_kernel<<<(BB*NN*HID + 255)/256, 256>>>(yh, W_dw, b_dw, zh);

    // 9) out = h2 + gate_mlp*(z@W_pt^T) -> f32
    gemm_f16<4,float><<<gq, 256>>>(zh, wpt, nullptr, out, HID, DIM, h2, temb, sst, 5);
}